// round 5
// baseline (speedup 1.0000x reference)
#include <cuda_runtime.h>

// Shapes: lx_in/ux_in (32768 rows x 1024 fp32), lc/uc (32768), x_min/x_max (1024).
// Outputs concatenated in d_out: [lx_out | ux_out | lc_out | uc_out].
//
// Persistent grid (grid = SMs x resident blocks, queried at launch).
// Each block grid-strides over ROW PAIRS: 2 rows per iteration,
// prefetch of the next pair issued before the current pair's reduction,
// one __syncthreads per pair (parity double-buffered partials).
// mn/mx tables live in registers for the whole kernel.

#define NROWS 32768
#define INNER 1024
#define NTHREADS 256
#define NWARPS (NTHREADS / 32)
#define NPAIRS (NROWS / 2)          // 16384
#define F4 (INNER / 4)              // 256 float4 per row

__global__ __launch_bounds__(NTHREADS)
void crown_relu_persist(const float* __restrict__ lx_in,
                        const float* __restrict__ ux_in,
                        const float* __restrict__ lc_in,
                        const float* __restrict__ uc_in,
                        const float* __restrict__ x_min,
                        const float* __restrict__ x_max,
                        float* __restrict__ lx_out,
                        float* __restrict__ ux_out,
                        float* __restrict__ lc_out,
                        float* __restrict__ uc_out)
{
    const int t    = threadIdx.x;
    const int lane = t & 31;
    const int wid  = t >> 5;

    const float4* __restrict__ lx4 = reinterpret_cast<const float4*>(lx_in);
    const float4* __restrict__ ux4 = reinterpret_cast<const float4*>(ux_in);
    float4* __restrict__ lo4 = reinterpret_cast<float4*>(lx_out);
    float4* __restrict__ uo4 = reinterpret_cast<float4*>(ux_out);

    // Hot 8KB tables -> registers for the whole persistent lifetime.
    const float4 mn = __ldg(reinterpret_cast<const float4*>(x_min) + t);
    const float4 mx = __ldg(reinterpret_cast<const float4*>(x_max) + t);

    __shared__ float s_l[2][2][NWARPS];   // [parity][row-in-pair][warp]
    __shared__ float s_u[2][2][NWARPS];

    const int stride = gridDim.x;

    // Prologue: load first pair.
    int pair = blockIdx.x;
    float4 lv0, uv0, lv1, uv1;
    {
        const long long b = (long long)pair * (2 * F4) + t;
        lv0 = __ldcs(lx4 + b);
        uv0 = __ldcs(ux4 + b);
        lv1 = __ldcs(lx4 + b + F4);
        uv1 = __ldcs(ux4 + b + F4);
    }

    int k = 0;
    for (; pair < NPAIRS; pair += stride, k++) {
        const long long cur = (long long)pair * (2 * F4) + t;
        const int nxt_pair = pair + stride;

        // Prefetch next pair before any dependent work: 4 LDG.128 in flight
        // across the shuffle/barrier/store phase below.
        float4 plv0, puv0, plv1, puv1;
        if (nxt_pair < NPAIRS) {
            const long long nb = (long long)nxt_pair * (2 * F4) + t;
            plv0 = __ldcs(lx4 + nb);
            puv0 = __ldcs(ux4 + nb);
            plv1 = __ldcs(lx4 + nb + F4);
            puv1 = __ldcs(ux4 + nb + F4);
        }

        // mask_lower*lx == min(lx*mn, lx*mx); mask_upper*ux == max(...)
        float sl0 = fminf(lv0.x * mn.x, lv0.x * mx.x)
                  + fminf(lv0.y * mn.y, lv0.y * mx.y)
                  + fminf(lv0.z * mn.z, lv0.z * mx.z)
                  + fminf(lv0.w * mn.w, lv0.w * mx.w);
        float su0 = fmaxf(uv0.x * mn.x, uv0.x * mx.x)
                  + fmaxf(uv0.y * mn.y, uv0.y * mx.y)
                  + fmaxf(uv0.z * mn.z, uv0.z * mx.z)
                  + fmaxf(uv0.w * mn.w, uv0.w * mx.w);
        float sl1 = fminf(lv1.x * mn.x, lv1.x * mx.x)
                  + fminf(lv1.y * mn.y, lv1.y * mx.y)
                  + fminf(lv1.z * mn.z, lv1.z * mx.z)
                  + fminf(lv1.w * mn.w, lv1.w * mx.w);
        float su1 = fmaxf(uv1.x * mn.x, uv1.x * mx.x)
                  + fmaxf(uv1.y * mn.y, uv1.y * mx.y)
                  + fmaxf(uv1.z * mn.z, uv1.z * mx.z)
                  + fmaxf(uv1.w * mn.w, uv1.w * mx.w);

        #pragma unroll
        for (int o = 16; o > 0; o >>= 1) {
            sl0 += __shfl_xor_sync(0xffffffffu, sl0, o);
            su0 += __shfl_xor_sync(0xffffffffu, su0, o);
            sl1 += __shfl_xor_sync(0xffffffffu, sl1, o);
            su1 += __shfl_xor_sync(0xffffffffu, su1, o);
        }

        const int p = k & 1;
        if (lane == 0) {
            s_l[p][0][wid] = sl0; s_u[p][0][wid] = su0;
            s_l[p][1][wid] = sl1; s_u[p][1][wid] = su1;
        }
        __syncthreads();   // one barrier per 2 rows

        const int row0 = pair * 2;
        const float lc0 = lc_in[row0],     uc0 = uc_in[row0];
        const float lc1 = lc_in[row0 + 1], uc1 = uc_in[row0 + 1];
        float l0 = lc0, u0 = uc0, l1 = lc1, u1 = uc1;
        #pragma unroll
        for (int w = 0; w < NWARPS; w++) {
            l0 += s_l[p][0][w]; u0 += s_u[p][0][w];
            l1 += s_l[p][1][w]; u1 += s_u[p][1][w];
        }

        const bool  al0 = (l0 >= 0.0f);
        const bool  cr0 = (l0 < 0.0f) && (u0 > 0.0f);
        const float sp0 = cr0 ? fminf(fmaxf(u0 / (u0 - l0), 0.0f), 1.0f) : 1.0f;
        const float fl0 = al0 ? 1.0f : 0.0f;
        const float fu0 = al0 ? 1.0f : (cr0 ? sp0 : 0.0f);

        const bool  al1 = (l1 >= 0.0f);
        const bool  cr1 = (l1 < 0.0f) && (u1 > 0.0f);
        const float sp1 = cr1 ? fminf(fmaxf(u1 / (u1 - l1), 0.0f), 1.0f) : 1.0f;
        const float fl1 = al1 ? 1.0f : 0.0f;
        const float fu1 = al1 ? 1.0f : (cr1 ? sp1 : 0.0f);

        if (t == 0) {
            lc_out[row0] = fl0 * lc0;
            uc_out[row0] = al0 ? uc0 : (cr0 ? (sp0 * uc0 - sp0 * l0) : 0.0f);
        } else if (t == 32) {
            lc_out[row0 + 1] = fl1 * lc1;
            uc_out[row0 + 1] = al1 ? uc1 : (cr1 ? (sp1 * uc1 - sp1 * l1) : 0.0f);
        }

        float4 a, b;
        a.x = fl0 * lv0.x; a.y = fl0 * lv0.y; a.z = fl0 * lv0.z; a.w = fl0 * lv0.w;
        b.x = fu0 * uv0.x; b.y = fu0 * uv0.y; b.z = fu0 * uv0.z; b.w = fu0 * uv0.w;
        __stcs(lo4 + cur, a);
        __stcs(uo4 + cur, b);
        a.x = fl1 * lv1.x; a.y = fl1 * lv1.y; a.z = fl1 * lv1.z; a.w = fl1 * lv1.w;
        b.x = fu1 * uv1.x; b.y = fu1 * uv1.y; b.z = fu1 * uv1.z; b.w = fu1 * uv1.w;
        __stcs(lo4 + cur + F4, a);
        __stcs(uo4 + cur + F4, b);

        lv0 = plv0; uv0 = puv0; lv1 = plv1; uv1 = puv1;
    }
}

extern "C" void kernel_launch(void* const* d_in, const int* in_sizes, int n_in,
                              void* d_out, int out_size)
{
    const float* lx_in = (const float*)d_in[0];
    const float* ux_in = (const float*)d_in[1];
    const float* lc_in = (const float*)d_in[2];
    const float* uc_in = (const float*)d_in[3];
    const float* x_min = (const float*)d_in[4];
    const float* x_max = (const float*)d_in[5];

    float* out = (float*)d_out;
    const long long big = (long long)NROWS * INNER;   // 33,554,432
    float* lx_out = out;
    float* ux_out = out + big;
    float* lc_out = out + 2 * big;
    float* uc_out = out + 2 * big + NROWS;

    // Exact persistent grid: resident blocks per SM x SM count.
    int dev = 0, sms = 0, blocks_per_sm = 0;
    cudaGetDevice(&dev);
    cudaDeviceGetAttribute(&sms, cudaDevAttrMultiProcessorCount, dev);
    cudaOccupancyMaxActiveBlocksPerMultiprocessor(&blocks_per_sm,
                                                  crown_relu_persist,
                                                  NTHREADS, /*smem*/ 512);
    int grid = sms * (blocks_per_sm > 0 ? blocks_per_sm : 1);
    if (grid > NPAIRS) grid = NPAIRS;

    crown_relu_persist<<<grid, NTHREADS>>>(lx_in, ux_in, lc_in, uc_in,
                                           x_min, x_max,
                                           lx_out, ux_out, lc_out, uc_out);
}